// round 6
// baseline (speedup 1.0000x reference)
#include <cuda_runtime.h>
#include <cuda_bf16.h>
#include <cstdint>

#define BB 32
#define TT 512
#define KK 256
#define NR 4              // cluster size = i-split ways
#define IPC (KK / NR)     // 64 i-rows per CTA
#define NWORD (IPC / 2)   // 32 bf16x2 table words per thread

__device__ float g_partial[BB];

static __device__ __forceinline__ unsigned int f2bf_rn(float x) {
    unsigned int u = __float_as_uint(x);
    return (u + 0x7FFFu + ((u >> 16) & 1u)) >> 16;
}

#define HFMA2_BF16(d, a, b, c) \
    asm("fma.rn.bf16x2 %0, %1, %2, %3;" : "=r"(d) : "r"(a), "r"(b), "r"(c))

static __device__ __forceinline__ unsigned smem_u32(const void* p) {
    return (unsigned)__cvta_generic_to_shared(p);
}
static __device__ __forceinline__ unsigned mapa_u32(unsigned a, unsigned r) {
    unsigned d;
    asm("mapa.shared::cluster.u32 %0, %1, %2;" : "=r"(d) : "r"(a), "r"(r));
    return d;
}
static __device__ __forceinline__ unsigned ctarank() {
    unsigned r; asm("mov.u32 %0, %%cluster_ctarank;" : "=r"(r)); return r;
}

#define MBAR_INIT(addr, cnt) \
    asm volatile("mbarrier.init.shared.b64 [%0], %1;" :: "r"(addr), "r"(cnt) : "memory")
#define MBAR_EXPECT_TX(addr, bytes) \
    asm volatile("mbarrier.arrive.expect_tx.shared.b64 _, [%0], %1;" :: "r"(addr), "r"(bytes) : "memory")
#define ST_ASYNC_F32(raddr, val, rmbar) \
    asm volatile("st.async.shared::cluster.mbarrier::complete_tx::bytes.b32 [%0], %1, [%2];" \
                 :: "r"(raddr), "r"(__float_as_uint(val)), "r"(rmbar) : "memory")
#define MBAR_WAIT_CLUSTER(mbar, ph) do {                                              \
    unsigned _done;                                                                   \
    asm volatile("{\n\t.reg .pred p;\n\t"                                             \
        "mbarrier.try_wait.parity.acquire.cluster.shared::cta.b64 p, [%1], %2;\n\t"   \
        "selp.b32 %0, 1, 0, p;\n\t}"                                                  \
        : "=r"(_done) : "r"(mbar), "r"(ph) : "memory");                               \
    while (!_done) {                                                                  \
        asm volatile("{\n\t.reg .pred p;\n\t"                                         \
            "mbarrier.try_wait.parity.acquire.cluster.shared::cta.b64 p, [%1], %2, 0x989680;\n\t" \
            "selp.b32 %0, 1, 0, p;\n\t}"                                              \
            : "=r"(_done) : "r"(mbar), "r"(ph) : "memory");                           \
    }                                                                                 \
} while (0)

// ---------------------------------------------------------------------------
// One 4-CTA cluster per batch element. Each CTA: 256 threads, thread j owns
// column j; holds expT[rank*64 .. rank*64+63][j] in 32 bf16x2 registers.
// Per step: local partial dot over 64 i's -> st.async fp32 partial to the 3
// peers -> mbarrier wait -> fixed-order combine -> replicated alpha update.
// Normalizer c = thread 0's alpha lagged 2 steps (replicated, race-free).
// ---------------------------------------------------------------------------
__global__ void __launch_bounds__(256, 1) __cluster_dims__(NR, 1, 1)
crf_main(const float* __restrict__ emissions,
         const int*   __restrict__ tags,
         const int*   __restrict__ mask,
         const float* __restrict__ trans)
{
    __shared__ unsigned short sh_e[2][KK];        // exp(alpha-c), bf16, 2 stages
    __shared__ float sh_part[2][KK][NR];          // incoming partials, 2 stages
    __shared__ float sh_c[2];                     // lagged normalizer
    __shared__ float sh_red[12];                  // reductions (+slot 8 = log_num)
    __shared__ unsigned long long sh_mbar[2];

    const int b    = blockIdx.x >> 2;             // cluster id = batch
    const unsigned rank = ctarank();
    const int j    = threadIdx.x;
    const int lane = j & 31;
    const int wid  = j >> 5;

    // ---- build my expT slice in registers: word w = exp(trans) rows (rank*64+2w, +1), col j ----
    unsigned int tab[NWORD];
    #pragma unroll
    for (int w = 0; w < NWORD; ++w) {
        int i0 = (int)rank * IPC + 2 * w;
        unsigned lo = f2bf_rn(__expf(trans[i0 * KK + j]));
        unsigned hi = f2bf_rn(__expf(trans[(i0 + 1) * KK + j]));
        tab[w] = lo | (hi << 16);
    }

    // ---- joint (numerator) score (replicated; rank 0 result used) ----
    float js = 0.0f;
    #pragma unroll
    for (int h = 0; h < 2; ++h) {
        int t = j + h * 256;
        if (mask[b * TT + t] != 0) {
            int tag = tags[b * TT + t];
            js += emissions[((size_t)b * TT + t) * KK + tag];
            if (t >= 1) js += trans[tags[b * TT + t - 1] * KK + tag];
        }
    }
    #pragma unroll
    for (int s = 16; s; s >>= 1) js += __shfl_xor_sync(0xFFFFFFFFu, js, s);
    if (lane == 0) sh_red[wid] = js;
    __syncthreads();
    if (j == 0) {
        float s = 0.0f;
        #pragma unroll
        for (int w = 0; w < 8; ++w) s += sh_red[w];
        sh_red[8] = s;
    }

    // ---- init recursion state ----
    const float* em_b = emissions + (size_t)b * TT * KK;
    float alpha = em_b[j];
    if (j == 0) {
        sh_c[0] = alpha; sh_c[1] = alpha;
        MBAR_INIT(smem_u32(&sh_mbar[0]), 1);
        MBAR_INIT(smem_u32(&sh_mbar[1]), 1);
    }
    __syncthreads();
    // cluster-wide: all mbarriers initialized before any st.async
    asm volatile("barrier.cluster.arrive.aligned;" ::: "memory");
    asm volatile("barrier.cluster.wait.aligned;"   ::: "memory");

    // ---- precompute remote addresses (my slot in each peer's sh_part; peer mbars) ----
    unsigned lp0 = smem_u32(&sh_part[0][j][rank]);
    unsigned lp1 = smem_u32(&sh_part[1][j][rank]);
    unsigned mb[2] = { smem_u32(&sh_mbar[0]), smem_u32(&sh_mbar[1]) };
    unsigned rp0[3], rp1[3], rm0[3], rm1[3];
    #pragma unroll
    for (int p = 0; p < 3; ++p) {
        unsigned pr = (rank + 1 + p) & 3;
        rp0[p] = mapa_u32(lp0, pr);  rp1[p] = mapa_u32(lp1, pr);
        rm0[p] = mapa_u32(mb[0], pr); rm1[p] = mapa_u32(mb[1], pr);
    }

    int ph0 = 0, ph1 = 0;

    for (int t = 1; t < TT; ++t) {
        const int buf = t & 1;
        float emit = em_b[t * KK + j];            // prefetch
        int   mv   = mask[b * TT + t];

        float c = sh_c[buf];                      // lagged by 2 steps
        sh_e[buf][j] = (unsigned short)f2bf_rn(__expf(alpha - c));
        __syncthreads();
        if (j == 0) MBAR_EXPECT_TX(mb[buf], 3 * KK * 4);

        // ---- partial dot over my 64 i's ----
        const uint4* eb4 = (const uint4*)(&sh_e[buf][rank * IPC]);
        float acc0 = 0.0f, acc1 = 0.0f;
        #pragma unroll
        for (int g = 0; g < 4; ++g) {
            uint4 e0 = eb4[2 * g];
            uint4 e1 = eb4[2 * g + 1];
            unsigned int a2 = 0u;
            HFMA2_BF16(a2, e0.x, tab[8 * g + 0], a2);
            HFMA2_BF16(a2, e0.y, tab[8 * g + 1], a2);
            HFMA2_BF16(a2, e0.z, tab[8 * g + 2], a2);
            HFMA2_BF16(a2, e0.w, tab[8 * g + 3], a2);
            HFMA2_BF16(a2, e1.x, tab[8 * g + 4], a2);
            HFMA2_BF16(a2, e1.y, tab[8 * g + 5], a2);
            HFMA2_BF16(a2, e1.z, tab[8 * g + 6], a2);
            HFMA2_BF16(a2, e1.w, tab[8 * g + 7], a2);
            acc0 += __uint_as_float(a2 << 16);
            acc1 += __uint_as_float(a2 & 0xFFFF0000u);
        }
        float partial = acc0 + acc1;

        // ---- publish partial: local slot + st.async to the 3 peers ----
        sh_part[buf][j][rank] = partial;
        #pragma unroll
        for (int p = 0; p < 3; ++p) {
            unsigned ra = buf ? rp1[p] : rp0[p];
            unsigned rb = buf ? rm1[p] : rm0[p];
            ST_ASYNC_F32(ra, partial, rb);
        }

        if (buf) { MBAR_WAIT_CLUSTER(mb[1], ph1); ph1 ^= 1; }
        else     { MBAR_WAIT_CLUSTER(mb[0], ph0); ph0 ^= 1; }

        // ---- fixed-order combine (identical in every replica) ----
        float4 q = *(const float4*)&sh_part[buf][j][0];
        float acc  = (q.x + q.y) + (q.z + q.w);   // > 0 always
        float anew = c + __logf(acc) + emit;
        alpha = (mv != 0) ? anew : alpha;

        if (j == 0) sh_c[buf] = alpha;            // normalizer for step t+2
    }

    // ---- final logsumexp over alpha (exact, fp32; replicated) ----
    float m = alpha;
    #pragma unroll
    for (int s = 16; s; s >>= 1) m = fmaxf(m, __shfl_xor_sync(0xFFFFFFFFu, m, s));
    if (lane == 0) sh_red[wid] = m;
    __syncthreads();
    float c = sh_red[0];
    #pragma unroll
    for (int w = 1; w < 8; ++w) c = fmaxf(c, sh_red[w]);
    float e = __expf(alpha - c);
    #pragma unroll
    for (int s = 16; s; s >>= 1) e += __shfl_xor_sync(0xFFFFFFFFu, e, s);
    __syncthreads();
    if (lane == 0) sh_red[wid] = e;
    __syncthreads();
    if (j == 0 && rank == 0) {
        float s = 0.0f;
        #pragma unroll
        for (int w = 0; w < 8; ++w) s += sh_red[w];
        g_partial[b] = (c + __logf(s)) - sh_red[8];   // log_den - log_num
    }

    // keep SMEM alive until every peer consumed its last incoming writes
    asm volatile("barrier.cluster.arrive.aligned;" ::: "memory");
    asm volatile("barrier.cluster.wait.aligned;"   ::: "memory");
}

// ---------------------------------------------------------------------------
// Deterministic fixed-order mean over batch.
// ---------------------------------------------------------------------------
__global__ void crf_fin(float* __restrict__ out) {
    float s = 0.0f;
    #pragma unroll
    for (int b = 0; b < BB; ++b) s += g_partial[b];
    out[0] = s * (1.0f / (float)BB);
}

extern "C" void kernel_launch(void* const* d_in, const int* in_sizes, int n_in,
                              void* d_out, int out_size) {
    (void)in_sizes; (void)n_in; (void)out_size;
    const float* emissions = (const float*)d_in[0];
    const int*   tags      = (const int*)d_in[1];
    const int*   mask      = (const int*)d_in[2];
    const float* trans     = (const float*)d_in[3];

    crf_main<<<BB * NR, 256>>>(emissions, tags, mask, trans);
    crf_fin<<<1, 1>>>((float*)d_out);
}

// round 7
// speedup vs baseline: 2.2342x; 2.2342x over previous
#include <cuda_runtime.h>
#include <cuda_bf16.h>
#include <cstdint>

#define BB 32
#define TT 512
#define KK 256

__device__ float g_partial[BB];
__device__ unsigned int g_count;   // zero-init; returns to zero every launch

static __device__ __forceinline__ unsigned int f2bf_rn(float x) {
    unsigned int u = __float_as_uint(x);
    return (u + 0x7FFFu + ((u >> 16) & 1u)) >> 16;
}

#define HFMA2_BF16(d, a, b, c) \
    asm("fma.rn.bf16x2 %0, %1, %2, %3;" : "=r"(d) : "r"(a), "r"(b), "r"(c))

// ---------------------------------------------------------------------------
// One CTA per batch element, 256 threads, thread j owns column j and holds
// expT[:, j] as 128 bf16x2 registers.
//
// State: E_j = exp(alpha_j - n), n replicated & implicit. Per step:
//   store E (bf16) -> sync -> rho = rcp(E[0]) (new normalizer ratio)
//   acc_j = sum_i E_i * expT[i][j]        (bf16x2 HFMA2, fp32 flush per 16)
//   E_j' = mask ? acc_j * (exp(emit_j)*rho) : E_j * rho
// n is recovered at the end from the running product of the stored E[0]
// values via exponent extraction (no per-step log/exp on the critical path).
// ---------------------------------------------------------------------------
__global__ void __launch_bounds__(256, 1) crf_main(
    const float* __restrict__ emissions,
    const int*   __restrict__ tags,
    const int*   __restrict__ mask,
    const float* __restrict__ trans,
    float*       __restrict__ out)
{
    __shared__ __align__(16) unsigned short sh_e[2][KK];  // E as bf16, 2 stages
    __shared__ float sh_red[12];   // [0..7] scratch, [8] log_num, [9] nbase

    const int b    = blockIdx.x;
    const int j    = threadIdx.x;
    const int lane = j & 31;
    const int wid  = j >> 5;

    // ---- build expT column j in registers (one-time; trans is L2-hot) ----
    unsigned int tab[128];
    #pragma unroll
    for (int w = 0; w < 128; ++w) {
        unsigned lo = f2bf_rn(__expf(trans[(2 * w)     * KK + j]));
        unsigned hi = f2bf_rn(__expf(trans[(2 * w + 1) * KK + j]));
        tab[w] = lo | (hi << 16);
    }

    // ---- joint (numerator) score ----
    float js = 0.0f;
    #pragma unroll
    for (int h = 0; h < 2; ++h) {
        int t = j + h * 256;
        if (mask[b * TT + t] != 0) {
            int tag = tags[b * TT + t];
            js += emissions[((size_t)b * TT + t) * KK + tag];
            if (t >= 1) js += trans[tags[b * TT + t - 1] * KK + tag];
        }
    }
    #pragma unroll
    for (int s = 16; s; s >>= 1) js += __shfl_xor_sync(0xFFFFFFFFu, js, s);
    if (lane == 0) sh_red[wid] = js;

    // ---- init: alpha0 = emissions[b,0,:]; nbase = alpha0[0] ----
    const float* em_b = emissions + (size_t)b * TT * KK;
    float a0 = em_b[j];
    __syncthreads();
    if (j == 0) {
        float s = 0.0f;
        #pragma unroll
        for (int w = 0; w < 8; ++w) s += sh_red[w];
        sh_red[8] = s;            // log_num
        sh_red[9] = a0;           // nbase (thread 0's alpha0)
    }
    __syncthreads();
    const float nbase = sh_red[9];

    float E    = __expf(a0 - nbase);  // E_0 (thread 0: exactly 1.0)
    float prod = 1.0f;                // running product of stored E[0] values
    int   cnt  = 0;                   // extracted binary exponent sum

    // software-pipelined emit/mask prefetch (1 step ahead)
    float emit = em_b[KK + j];
    int   mv   = mask[b * TT + 1];

    for (int t = 1; t < TT; ++t) {
        const int buf = t & 1;
        // prefetch step t+1 inputs (clamped)
        int tn = (t + 1 < TT) ? (t + 1) : (TT - 1);
        float emit_n = em_b[tn * KK + j];
        int   mv_n   = mask[b * TT + tn];

        float wexp = __expf(emit);                 // off critical path

        sh_e[buf][j] = (unsigned short)f2bf_rn(E);
        __syncthreads();

        // normalizer ratio: rho = 1 / (stored E[0])   (broadcast LDS + MUFU RCP)
        float v = __uint_as_float(((unsigned)sh_e[buf][0]) << 16);
        float rho;
        asm("rcp.approx.f32 %0, %1;" : "=f"(rho) : "f"(v));
        float wr = wexp * rho;                     // also off critical path

        // ---- dot: acc_j = sum_i E_i * expT[i][j] ----
        const uint4* eb4 = (const uint4*)sh_e[buf];
        float acc0 = 0.0f, acc1 = 0.0f;
        #pragma unroll
        for (int g = 0; g < 8; ++g) {
            uint4 ea = eb4[4 * g + 0];
            uint4 eb = eb4[4 * g + 1];
            uint4 ec = eb4[4 * g + 2];
            uint4 ed = eb4[4 * g + 3];
            unsigned int a2 = 0u;
            HFMA2_BF16(a2, ea.x, tab[16 * g +  0], a2);
            HFMA2_BF16(a2, ea.y, tab[16 * g +  1], a2);
            HFMA2_BF16(a2, ea.z, tab[16 * g +  2], a2);
            HFMA2_BF16(a2, ea.w, tab[16 * g +  3], a2);
            HFMA2_BF16(a2, eb.x, tab[16 * g +  4], a2);
            HFMA2_BF16(a2, eb.y, tab[16 * g +  5], a2);
            HFMA2_BF16(a2, eb.z, tab[16 * g +  6], a2);
            HFMA2_BF16(a2, eb.w, tab[16 * g +  7], a2);
            HFMA2_BF16(a2, ec.x, tab[16 * g +  8], a2);
            HFMA2_BF16(a2, ec.y, tab[16 * g +  9], a2);
            HFMA2_BF16(a2, ec.z, tab[16 * g + 10], a2);
            HFMA2_BF16(a2, ec.w, tab[16 * g + 11], a2);
            HFMA2_BF16(a2, ed.x, tab[16 * g + 12], a2);
            HFMA2_BF16(a2, ed.y, tab[16 * g + 13], a2);
            HFMA2_BF16(a2, ed.z, tab[16 * g + 14], a2);
            HFMA2_BF16(a2, ed.w, tab[16 * g + 15], a2);
            acc0 += __uint_as_float(a2 << 16);          // low bf16 lane
            acc1 += __uint_as_float(a2 & 0xFFFF0000u);  // high bf16 lane
        }
        float acc = acc0 + acc1;                   // > 0 always

        // ---- state update: single FMUL tail ----
        E = mv ? (acc * wr) : (E * rho);

        // ---- replicated normalizer tracking (exact, no MUFU) ----
        prod *= v;
        unsigned up = __float_as_uint(prod);
        cnt += (int)(up >> 23) - 127;
        prod = __uint_as_float((up & 0x007FFFFFu) | 0x3F800000u);

        emit = emit_n; mv = mv_n;
    }

    // ---- final: log_den = n_final + log(sum_j E_j) ----
    float e = E;
    #pragma unroll
    for (int s = 16; s; s >>= 1) e += __shfl_xor_sync(0xFFFFFFFFu, e, s);
    if (lane == 0) sh_red[wid] = e;
    __syncthreads();
    if (j == 0) {
        float tot = 0.0f;
        #pragma unroll
        for (int w = 0; w < 8; ++w) tot += sh_red[w];
        // n_final = nbase + cnt*ln2 + log(prod), split-constant for accuracy
        float cf   = (float)cnt;
        float nfin = nbase + cf * 0.693359375f
                   + (cf * -2.1219444e-4f + __logf(prod));
        float logden = nfin + __logf(tot);
        g_partial[b] = logden - sh_red[8];

        __threadfence();
        unsigned old = atomicAdd(&g_count, 1u);
        if (old == BB - 1) {
            g_count = 0;                       // reset for next launch/replay
            __threadfence();
            float ssum = 0.0f;
            #pragma unroll
            for (int x = 0; x < BB; ++x) ssum += g_partial[x];
            out[0] = ssum * (1.0f / (float)BB);
        }
    }
}

extern "C" void kernel_launch(void* const* d_in, const int* in_sizes, int n_in,
                              void* d_out, int out_size) {
    (void)in_sizes; (void)n_in; (void)out_size;
    const float* emissions = (const float*)d_in[0];
    const int*   tags      = (const int*)d_in[1];
    const int*   mask      = (const int*)d_in[2];
    const float* trans     = (const float*)d_in[3];

    crf_main<<<BB, 256>>>(emissions, tags, mask, trans, (float*)d_out);
}

// round 8
// speedup vs baseline: 2.5502x; 1.1414x over previous
#include <cuda_runtime.h>
#include <cuda_bf16.h>
#include <cstdint>

#define BB 32
#define TT 512
#define KK 256

__device__ float g_partial[BB];
__device__ unsigned int g_count;   // zero-init; returns to zero every launch

static __device__ __forceinline__ unsigned int f2bf_rn(float x) {
    unsigned int u = __float_as_uint(x);
    return (u + 0x7FFFu + ((u >> 16) & 1u)) >> 16;
}

#define HFMA2_BF16(d, a, b, c) \
    asm("fma.rn.bf16x2 %0, %1, %2, %3;" : "=r"(d) : "r"(a), "r"(b), "r"(c))

// ---------------------------------------------------------------------------
// One CTA per batch element, 256 threads, thread j owns column j and holds
// expT[:, j] as 128 bf16x2 registers.
//
// State: E_j = exp(alpha_j - n), n replicated & implicit. Per step:
//   store E (bf16) -> sync -> rho = rcp(E[0]);  wr = exp(emit)*rho; Erho = E*rho
//   acc_j = sum_i E_i * expT[i][j]   (4 chains of 32 bf16x2 HFMA2)
//   E_j' = mask ? acc_j * wr : Erho
// n recovered at the end from the running product of stored E[0] values via
// exponent extraction (no per-step log/exp on the critical path).
// ---------------------------------------------------------------------------
__global__ void __launch_bounds__(256, 1) crf_main(
    const float* __restrict__ emissions,
    const int*   __restrict__ tags,
    const int*   __restrict__ mask,
    const float* __restrict__ trans,
    float*       __restrict__ out)
{
    __shared__ __align__(16) unsigned short sh_e[2][KK];  // E as bf16, 2 stages
    __shared__ float sh_red[12];   // [0..7] scratch, [8] log_num, [9] nbase

    const int b    = blockIdx.x;
    const int j    = threadIdx.x;
    const int lane = j & 31;
    const int wid  = j >> 5;

    // ---- build expT column j in registers ----
    unsigned int tab[128];
    #pragma unroll
    for (int w = 0; w < 128; ++w) {
        unsigned lo = f2bf_rn(__expf(trans[(2 * w)     * KK + j]));
        unsigned hi = f2bf_rn(__expf(trans[(2 * w + 1) * KK + j]));
        tab[w] = lo | (hi << 16);
    }

    // ---- joint (numerator) score ----
    float js = 0.0f;
    #pragma unroll
    for (int h = 0; h < 2; ++h) {
        int t = j + h * 256;
        if (mask[b * TT + t] != 0) {
            int tag = tags[b * TT + t];
            js += emissions[((size_t)b * TT + t) * KK + tag];
            if (t >= 1) js += trans[tags[b * TT + t - 1] * KK + tag];
        }
    }
    #pragma unroll
    for (int s = 16; s; s >>= 1) js += __shfl_xor_sync(0xFFFFFFFFu, js, s);
    if (lane == 0) sh_red[wid] = js;

    // ---- init ----
    const float* em_b = emissions + (size_t)b * TT * KK;
    float a0 = em_b[j];
    __syncthreads();
    if (j == 0) {
        float s = 0.0f;
        #pragma unroll
        for (int w = 0; w < 8; ++w) s += sh_red[w];
        sh_red[8] = s;            // log_num
        sh_red[9] = a0;           // nbase
    }
    __syncthreads();
    const float nbase = sh_red[9];

    float E    = __expf(a0 - nbase);
    float prod = 1.0f;
    int   cnt  = 0;

    float emit = em_b[KK + j];            // prefetch t=1
    int   mv   = mask[b * TT + 1];

    // ---- one recursion step (buf is compile-time in the unrolled pairs) ----
    #define CRF_STEP(T_CUR, BUF)                                               \
    {                                                                          \
        int tn = ((T_CUR) + 1 < TT) ? ((T_CUR) + 1) : (TT - 1);                \
        float emit_n = em_b[tn * KK + j];                                      \
        int   mv_n   = mask[b * TT + tn];                                      \
        float wexp = __expf(emit);                                             \
        sh_e[BUF][j] = (unsigned short)f2bf_rn(E);                             \
        __syncthreads();                                                       \
        float v = __uint_as_float(((unsigned)sh_e[BUF][0]) << 16);             \
        float rho;                                                             \
        asm("rcp.approx.f32 %0, %1;" : "=f"(rho) : "f"(v));                    \
        float wr   = wexp * rho;                                               \
        float Erho = E * rho;                                                  \
        const uint4* eb4 = (const uint4*)sh_e[BUF];                            \
        unsigned int c0 = 0u, c1 = 0u, c2 = 0u, c3 = 0u;                       \
        _Pragma("unroll")                                                      \
        for (int q = 0; q < 8; ++q) {                                          \
            uint4 ea = eb4[q];                                                 \
            HFMA2_BF16(c0, ea.x, tab[4 * q + 0], c0);                          \
            HFMA2_BF16(c0, ea.y, tab[4 * q + 1], c0);                          \
            HFMA2_BF16(c0, ea.z, tab[4 * q + 2], c0);                          \
            HFMA2_BF16(c0, ea.w, tab[4 * q + 3], c0);                          \
            uint4 eb = eb4[8 + q];                                             \
            HFMA2_BF16(c1, eb.x, tab[32 + 4 * q + 0], c1);                     \
            HFMA2_BF16(c1, eb.y, tab[32 + 4 * q + 1], c1);                     \
            HFMA2_BF16(c1, eb.z, tab[32 + 4 * q + 2], c1);                     \
            HFMA2_BF16(c1, eb.w, tab[32 + 4 * q + 3], c1);                     \
            uint4 ec = eb4[16 + q];                                            \
            HFMA2_BF16(c2, ec.x, tab[64 + 4 * q + 0], c2);                     \
            HFMA2_BF16(c2, ec.y, tab[64 + 4 * q + 1], c2);                     \
            HFMA2_BF16(c2, ec.z, tab[64 + 4 * q + 2], c2);                     \
            HFMA2_BF16(c2, ec.w, tab[64 + 4 * q + 3], c2);                     \
            uint4 ed = eb4[24 + q];                                            \
            HFMA2_BF16(c3, ed.x, tab[96 + 4 * q + 0], c3);                     \
            HFMA2_BF16(c3, ed.y, tab[96 + 4 * q + 1], c3);                     \
            HFMA2_BF16(c3, ed.z, tab[96 + 4 * q + 2], c3);                     \
            HFMA2_BF16(c3, ed.w, tab[96 + 4 * q + 3], c3);                     \
        }                                                                      \
        float s01 = (__uint_as_float(c0 << 16) + __uint_as_float(c0 & 0xFFFF0000u)) \
                  + (__uint_as_float(c1 << 16) + __uint_as_float(c1 & 0xFFFF0000u)); \
        float s23 = (__uint_as_float(c2 << 16) + __uint_as_float(c2 & 0xFFFF0000u)) \
                  + (__uint_as_float(c3 << 16) + __uint_as_float(c3 & 0xFFFF0000u)); \
        float acc = s01 + s23;                                                 \
        E = mv ? (acc * wr) : Erho;                                            \
        prod *= v;                                                             \
        unsigned up = __float_as_uint(prod);                                   \
        cnt += (int)(up >> 23) - 127;                                          \
        prod = __uint_as_float((up & 0x007FFFFFu) | 0x3F800000u);              \
        emit = emit_n; mv = mv_n;                                              \
    }

    // t = 1 standalone (odd step count: 511 steps total)
    CRF_STEP(1, 1)
    // pairs (2,3), (4,5), ..., (510, 511)
    for (int t = 2; t < TT; t += 2) {
        CRF_STEP(t, 0)
        CRF_STEP(t + 1, 1)
    }
    #undef CRF_STEP

    // ---- final: log_den = n_final + log(sum_j E_j) ----
    float e = E;
    #pragma unroll
    for (int s = 16; s; s >>= 1) e += __shfl_xor_sync(0xFFFFFFFFu, e, s);
    if (lane == 0) sh_red[wid] = e;
    __syncthreads();
    if (j == 0) {
        float tot = 0.0f;
        #pragma unroll
        for (int w = 0; w < 8; ++w) tot += sh_red[w];
        float cf   = (float)cnt;
        float nfin = nbase + cf * 0.693359375f
                   + (cf * -2.1219444e-4f + __logf(prod));
        float logden = nfin + __logf(tot);
        g_partial[b] = logden - sh_red[8];

        __threadfence();
        unsigned old = atomicAdd(&g_count, 1u);
        if (old == BB - 1) {
            g_count = 0;
            __threadfence();
            float ssum = 0.0f;
            #pragma unroll
            for (int x = 0; x < BB; ++x) ssum += g_partial[x];
            out[0] = ssum * (1.0f / (float)BB);
        }
    }
}

extern "C" void kernel_launch(void* const* d_in, const int* in_sizes, int n_in,
                              void* d_out, int out_size) {
    (void)in_sizes; (void)n_in; (void)out_size;
    const float* emissions = (const float*)d_in[0];
    const int*   tags      = (const int*)d_in[1];
    const int*   mask      = (const int*)d_in[2];
    const float* trans     = (const float*)d_in[3];

    crf_main<<<BB, 256>>>(emissions, tags, mask, trans, (float*)d_out);
}

// round 9
// speedup vs baseline: 2.5945x; 1.0174x over previous
#include <cuda_runtime.h>
#include <cuda_bf16.h>
#include <cstdint>

#define BB 32
#define TT 512
#define KK 256

__device__ float g_partial[BB];
__device__ unsigned int g_count;   // zero-init; returns to zero every launch

static __device__ __forceinline__ unsigned int f2bf_rn(float x) {
    unsigned int u = __float_as_uint(x);
    return (u + 0x7FFFu + ((u >> 16) & 1u)) >> 16;
}

static __device__ __forceinline__ unsigned short cvt_bf16(float x) {
    unsigned short h;
    asm("cvt.rn.bf16.f32 %0, %1;" : "=h"(h) : "f"(x));
    return h;
}

#define HFMA2_BF16(d, a, b, c) \
    asm("fma.rn.bf16x2 %0, %1, %2, %3;" : "=r"(d) : "r"(a), "r"(b), "r"(c))

// ---------------------------------------------------------------------------
// One CTA per batch element, 256 threads, thread j owns column j and holds
// expT[:, j] as 128 bf16x2 registers.
//
// State: E_j = exp(alpha_j - n), n replicated & implicit. Per step:
//   store E (bf16) -> sync -> rho = rcp(E[0]);  wr = exp(emit)*rho; Erho = E*rho
//   acc_j = sum_i E_i * expT[i][j]   (4 chains of 32 bf16x2 HFMA2)
//   E_j' = mask ? acc_j * wr : Erho
// n recovered at the end from the running product of stored E[0] values via
// exponent extraction (no per-step log/exp on the critical path).
// ---------------------------------------------------------------------------
__global__ void __launch_bounds__(256, 1) crf_main(
    const float* __restrict__ emissions,
    const int*   __restrict__ tags,
    const int*   __restrict__ mask,
    const float* __restrict__ trans,
    float*       __restrict__ out)
{
    __shared__ __align__(16) unsigned short sh_e[2][KK];  // E as bf16, 2 stages
    __shared__ float sh_red[12];   // [0..7] scratch, [8] log_num, [9] nbase

    const int b    = blockIdx.x;
    const int j    = threadIdx.x;
    const int lane = j & 31;
    const int wid  = j >> 5;

    // ---- build expT column j in registers ----
    unsigned int tab[128];
    #pragma unroll
    for (int w = 0; w < 128; ++w) {
        unsigned lo = f2bf_rn(__expf(trans[(2 * w)     * KK + j]));
        unsigned hi = f2bf_rn(__expf(trans[(2 * w + 1) * KK + j]));
        tab[w] = lo | (hi << 16);
    }

    // ---- joint (numerator) score ----
    float js = 0.0f;
    #pragma unroll
    for (int h = 0; h < 2; ++h) {
        int t = j + h * 256;
        if (mask[b * TT + t] != 0) {
            int tag = tags[b * TT + t];
            js += emissions[((size_t)b * TT + t) * KK + tag];
            if (t >= 1) js += trans[tags[b * TT + t - 1] * KK + tag];
        }
    }
    #pragma unroll
    for (int s = 16; s; s >>= 1) js += __shfl_xor_sync(0xFFFFFFFFu, js, s);
    if (lane == 0) sh_red[wid] = js;

    // ---- init ----
    const float* em_b = emissions + (size_t)b * TT * KK;
    float a0 = em_b[j];
    __syncthreads();
    if (j == 0) {
        float s = 0.0f;
        #pragma unroll
        for (int w = 0; w < 8; ++w) s += sh_red[w];
        sh_red[8] = s;            // log_num
        sh_red[9] = a0;           // nbase
    }
    __syncthreads();
    const float nbase = sh_red[9];

    float E    = __expf(a0 - nbase);
    float prod = 1.0f;
    int   cnt  = 0;

    float emit = em_b[KK + j];            // prefetch t=1
    int   mv   = mask[b * TT + 1];

    // ---- one recursion step (BUF is compile-time everywhere) ----
    #define CRF_STEP(T_CUR, BUF)                                               \
    {                                                                          \
        int tn = ((T_CUR) + 1 < TT) ? ((T_CUR) + 1) : (TT - 1);                \
        float emit_n = em_b[tn * KK + j];                                      \
        int   mv_n   = mask[b * TT + tn];                                      \
        float wexp = __expf(emit);                                             \
        sh_e[BUF][j] = cvt_bf16(E);                                            \
        __syncthreads();                                                       \
        float v = __uint_as_float(((unsigned)sh_e[BUF][0]) << 16);             \
        float rho;                                                             \
        asm("rcp.approx.f32 %0, %1;" : "=f"(rho) : "f"(v));                    \
        float wr   = wexp * rho;                                               \
        float Erho = E * rho;                                                  \
        const uint4* eb4 = (const uint4*)sh_e[BUF];                            \
        unsigned int c0 = 0u, c1 = 0u, c2 = 0u, c3 = 0u;                       \
        _Pragma("unroll")                                                      \
        for (int q = 0; q < 8; ++q) {                                          \
            uint4 ea = eb4[q];                                                 \
            HFMA2_BF16(c0, ea.x, tab[4 * q + 0], c0);                          \
            HFMA2_BF16(c0, ea.y, tab[4 * q + 1], c0);                          \
            HFMA2_BF16(c0, ea.z, tab[4 * q + 2], c0);                          \
            HFMA2_BF16(c0, ea.w, tab[4 * q + 3], c0);                          \
            uint4 eb = eb4[8 + q];                                             \
            HFMA2_BF16(c1, eb.x, tab[32 + 4 * q + 0], c1);                     \
            HFMA2_BF16(c1, eb.y, tab[32 + 4 * q + 1], c1);                     \
            HFMA2_BF16(c1, eb.z, tab[32 + 4 * q + 2], c1);                     \
            HFMA2_BF16(c1, eb.w, tab[32 + 4 * q + 3], c1);                     \
            uint4 ec = eb4[16 + q];                                            \
            HFMA2_BF16(c2, ec.x, tab[64 + 4 * q + 0], c2);                     \
            HFMA2_BF16(c2, ec.y, tab[64 + 4 * q + 1], c2);                     \
            HFMA2_BF16(c2, ec.z, tab[64 + 4 * q + 2], c2);                     \
            HFMA2_BF16(c2, ec.w, tab[64 + 4 * q + 3], c2);                     \
            uint4 ed = eb4[24 + q];                                            \
            HFMA2_BF16(c3, ed.x, tab[96 + 4 * q + 0], c3);                     \
            HFMA2_BF16(c3, ed.y, tab[96 + 4 * q + 1], c3);                     \
            HFMA2_BF16(c3, ed.z, tab[96 + 4 * q + 2], c3);                     \
            HFMA2_BF16(c3, ed.w, tab[96 + 4 * q + 3], c3);                     \
        }                                                                      \
        float s01 = (__uint_as_float(c0 << 16) + __uint_as_float(c0 & 0xFFFF0000u)) \
                  + (__uint_as_float(c1 << 16) + __uint_as_float(c1 & 0xFFFF0000u)); \
        float s23 = (__uint_as_float(c2 << 16) + __uint_as_float(c2 & 0xFFFF0000u)) \
                  + (__uint_as_float(c3 << 16) + __uint_as_float(c3 & 0xFFFF0000u)); \
        float acc = s01 + s23;                                                 \
        E = mv ? (acc * wr) : Erho;                                            \
        prod *= v;                                                             \
        unsigned up = __float_as_uint(prod);                                   \
        cnt += (int)(up >> 23) - 127;                                          \
        prod = __uint_as_float((up & 0x007FFFFFu) | 0x3F800000u);              \
        emit = emit_n; mv = mv_n;                                              \
    }

    // peel t = 1, 2, 3 so the main loop is exactly 127 x 4 steps
    CRF_STEP(1, 1)
    CRF_STEP(2, 0)
    CRF_STEP(3, 1)
    // t = 4 .. 511 in fours (508 steps)
    for (int t = 4; t < TT; t += 4) {
        CRF_STEP(t,     0)
        CRF_STEP(t + 1, 1)
        CRF_STEP(t + 2, 0)
        CRF_STEP(t + 3, 1)
    }
    #undef CRF_STEP

    // ---- final: log_den = n_final + log(sum_j E_j) ----
    float e = E;
    #pragma unroll
    for (int s = 16; s; s >>= 1) e += __shfl_xor_sync(0xFFFFFFFFu, e, s);
    if (lane == 0) sh_red[wid] = e;
    __syncthreads();
    if (j == 0) {
        float tot = 0.0f;
        #pragma unroll
        for (int w = 0; w < 8; ++w) tot += sh_red[w];
        float cf   = (float)cnt;
        float nfin = nbase + cf * 0.693359375f
                   + (cf * -2.1219444e-4f + __logf(prod));
        float logden = nfin + __logf(tot);
        g_partial[b] = logden - sh_red[8];

        __threadfence();
        unsigned old = atomicAdd(&g_count, 1u);
        if (old == BB - 1) {
            g_count = 0;
            __threadfence();
            float ssum = 0.0f;
            #pragma unroll
            for (int x = 0; x < BB; ++x) ssum += g_partial[x];
            out[0] = ssum * (1.0f / (float)BB);
        }
    }
}

extern "C" void kernel_launch(void* const* d_in, const int* in_sizes, int n_in,
                              void* d_out, int out_size) {
    (void)in_sizes; (void)n_in; (void)out_size;
    const float* emissions = (const float*)d_in[0];
    const int*   tags      = (const int*)d_in[1];
    const int*   mask      = (const int*)d_in[2];
    const float* trans     = (const float*)d_in[3];

    crf_main<<<BB, 256>>>(emissions, tags, mask, trans, (float*)d_out);
}

// round 12
// speedup vs baseline: 3.0800x; 1.1871x over previous
#include <cuda_runtime.h>
#include <cuda_bf16.h>
#include <cstdint>

#define BB 32
#define TT 512
#define KK 256
#define HALF 128

__device__ float g_pair[BB * 2];   // per-(batch, rank) partial sums of E
__device__ float g_nfin[BB];       // replicated normalizer (rank 0 writes)
__device__ float g_js[BB];         // joint score (rank 0 writes)
__device__ unsigned int g_count;   // zero-init; reset every launch

static __device__ __forceinline__ unsigned int f2bf_rn(float x) {
    unsigned int u = __float_as_uint(x);
    return (u + 0x7FFFu + ((u >> 16) & 1u)) >> 16;
}
static __device__ __forceinline__ unsigned int cvt_bf16(float x) {
    unsigned short h;
    asm("cvt.rn.bf16.f32 %0, %1;" : "=h"(h) : "f"(x));
    return (unsigned int)h;
}

#define HFMA2_BF16(d, a, b, c) \
    asm("fma.rn.bf16x2 %0, %1, %2, %3;" : "=r"(d) : "r"(a), "r"(b), "r"(c))

static __device__ __forceinline__ unsigned smem_u32(const void* p) {
    return (unsigned)__cvta_generic_to_shared(p);
}
static __device__ __forceinline__ unsigned mapa_u32(unsigned a, unsigned r) {
    unsigned d;
    asm("mapa.shared::cluster.u32 %0, %1, %2;" : "=r"(d) : "r"(a), "r"(r));
    return d;
}
static __device__ __forceinline__ unsigned ctarank() {
    unsigned r; asm("mov.u32 %0, %%cluster_ctarank;" : "=r"(r)); return r;
}

#define MBAR_INIT(addr, cnt) \
    asm volatile("mbarrier.init.shared.b64 [%0], %1;" :: "r"(addr), "r"(cnt) : "memory")
#define MBAR_EXPECT_TX(addr, bytes) \
    asm volatile("mbarrier.arrive.expect_tx.shared.b64 _, [%0], %1;" :: "r"(addr), "r"(bytes) : "memory")
#define ST_ASYNC_U32(raddr, val, rmbar) \
    asm volatile("st.async.shared::cluster.mbarrier::complete_tx::bytes.b32 [%0], %1, [%2];" \
                 :: "r"(raddr), "r"(val), "r"(rmbar) : "memory")
#define MBAR_WAIT_CLUSTER(mbar, ph) do {                                              \
    unsigned _done;                                                                   \
    asm volatile("{\n\t.reg .pred p;\n\t"                                             \
        "mbarrier.try_wait.parity.acquire.cluster.shared::cta.b64 p, [%1], %2;\n\t"   \
        "selp.b32 %0, 1, 0, p;\n\t}"                                                  \
        : "=r"(_done) : "r"(mbar), "r"(ph) : "memory");                               \
    while (!_done) {                                                                  \
        asm volatile("{\n\t.reg .pred p;\n\t"                                         \
            "mbarrier.try_wait.parity.acquire.cluster.shared::cta.b64 p, [%1], %2, 0x989680;\n\t" \
            "selp.b32 %0, 1, 0, p;\n\t}"                                              \
            : "=r"(_done) : "r"(mbar), "r"(ph) : "memory");                           \
    }                                                                                 \
} while (0)

// ---------------------------------------------------------------------------
// 2-CTA cluster per batch; CTA rank r owns output columns r*128..r*128+127
// and holds the FULL 256-state expT column in 128 bf16x2 registers:
// own-half states in tab[0..63], peer-half states in tab[64..127].
// Per step: st.async my E half to the peer (first thing), local store, sync,
// dot part A over own-half states (16 uint4, tab[0..63]), mbarrier wait,
// dot part B over peer-half states (16 uint4, tab[64..127]), tail.
// expect_tx armed one phase ahead so arrivals never precede arming.
// ---------------------------------------------------------------------------
__global__ void __launch_bounds__(128, 1) __cluster_dims__(2, 1, 1)
crf_main(const float* __restrict__ emissions,
         const int*   __restrict__ tags,
         const int*   __restrict__ mask,
         const float* __restrict__ trans,
         float*       __restrict__ out)
{
    __shared__ __align__(16) unsigned short sh_e[2][KK];   // full E, 2 stages
    __shared__ float sh_red[8];
    __shared__ unsigned long long sh_mbar[2];

    const int b    = blockIdx.x >> 1;
    const unsigned rank = ctarank();
    const unsigned peer = rank ^ 1u;
    const int j    = threadIdx.x;           // 0..127
    const int lane = j & 31;
    const int wid  = j >> 5;
    const int cg   = (int)rank * HALF + j;  // my output column

    // ---- expT column cg: own-half states tab[0..63], peer-half tab[64..127] ----
    unsigned int tab[128];
    #pragma unroll
    for (int w = 0; w < 64; ++w) {
        int i0 = (int)rank * HALF + 2 * w;
        unsigned lo = f2bf_rn(__expf(trans[i0 * KK + cg]));
        unsigned hi = f2bf_rn(__expf(trans[(i0 + 1) * KK + cg]));
        tab[w] = lo | (hi << 16);
    }
    #pragma unroll
    for (int w = 0; w < 64; ++w) {
        int i0 = (int)peer * HALF + 2 * w;
        unsigned lo = f2bf_rn(__expf(trans[i0 * KK + cg]));
        unsigned hi = f2bf_rn(__expf(trans[(i0 + 1) * KK + cg]));
        tab[64 + w] = lo | (hi << 16);
    }

    // ---- joint (numerator) score, replicated; rank0 publishes ----
    float js = 0.0f;
    #pragma unroll
    for (int h = 0; h < 4; ++h) {
        int t = j + h * HALF;
        if (mask[b * TT + t] != 0) {
            int tag = tags[b * TT + t];
            js += emissions[((size_t)b * TT + t) * KK + tag];
            if (t >= 1) js += trans[tags[b * TT + t - 1] * KK + tag];
        }
    }
    #pragma unroll
    for (int s = 16; s; s >>= 1) js += __shfl_xor_sync(0xFFFFFFFFu, js, s);
    if (lane == 0) sh_red[wid] = js;

    // ---- init state ----
    const float* em_b = emissions + (size_t)b * TT * KK;
    const float nbase = em_b[0];            // alpha0[0], identical both CTAs
    float E    = __expf(em_b[cg] - nbase);  // E_0 for my column
    float prod = 1.0f;
    int   cnt  = 0;

    __syncthreads();
    float js_tot = 0.0f;
    unsigned mb0 = smem_u32(&sh_mbar[0]), mb1 = smem_u32(&sh_mbar[1]);
    if (j == 0) {
        #pragma unroll
        for (int w = 0; w < 4; ++w) js_tot += sh_red[w];
        MBAR_INIT(mb0, 1);
        MBAR_INIT(mb1, 1);
        // pre-arm BOTH stages (phase 0) before any peer send exists
        MBAR_EXPECT_TX(mb1, 64 * 4);   // first used at t=1
        MBAR_EXPECT_TX(mb0, 64 * 4);   // first used at t=2
    }
    __syncthreads();
    asm volatile("barrier.cluster.arrive.aligned;" ::: "memory");
    asm volatile("barrier.cluster.wait.aligned;"   ::: "memory");

    // remote addresses (even threads send the packed pair for cols cg, cg+1)
    unsigned ra0 = mapa_u32(smem_u32(&sh_e[0][0]) + (unsigned)cg * 2u, peer);
    unsigned ra1 = mapa_u32(smem_u32(&sh_e[1][0]) + (unsigned)cg * 2u, peer);
    unsigned rm0 = mapa_u32(mb0, peer), rm1 = mapa_u32(mb1, peer);

    int ph0 = 0, ph1 = 0;

    float emit = em_b[KK + cg];             // prefetch t=1
    int   mv   = mask[b * TT + 1];

    #define CRF_STEP(T_CUR, BUF)                                               \
    {                                                                          \
        int tn = ((T_CUR) + 1 < TT) ? ((T_CUR) + 1) : (TT - 1);                \
        float emit_n = em_b[tn * KK + cg];                                     \
        int   mv_n   = mask[b * TT + tn];                                      \
        float wexp = __expf(emit);                                             \
        /* send my E half to peer ASAP (peer's stage already armed) */         \
        unsigned bits = cvt_bf16(E);                                           \
        unsigned pb   = __shfl_down_sync(0xFFFFFFFFu, bits, 1);                \
        if (!(j & 1)) {                                                        \
            unsigned pk = bits | (pb << 16);                                   \
            ST_ASYNC_U32((BUF) ? ra1 : ra0, pk, (BUF) ? rm1 : rm0);            \
        }                                                                      \
        sh_e[BUF][cg] = (unsigned short)bits;                                  \
        __syncthreads();                                                       \
        /* part A: ALL 128 own-half states = 16 uint4, tab[0..63] */           \
        const uint4* ebA = (const uint4*)&sh_e[BUF][rank * HALF];              \
        unsigned int c0 = 0u, c1 = 0u;                                         \
        _Pragma("unroll")                                                      \
        for (int q = 0; q < 16; ++q) {                                         \
            uint4 ea = ebA[q];                                                 \
            HFMA2_BF16(c0, ea.x, tab[4 * q + 0], c0);                          \
            HFMA2_BF16(c1, ea.y, tab[4 * q + 1], c1);                          \
            HFMA2_BF16(c0, ea.z, tab[4 * q + 2], c0);                          \
            HFMA2_BF16(c1, ea.w, tab[4 * q + 3], c1);                          \
        }                                                                      \
        float accA = (__uint_as_float(c0 << 16) + __uint_as_float(c0 & 0xFFFF0000u)) \
                   + (__uint_as_float(c1 << 16) + __uint_as_float(c1 & 0xFFFF0000u)); \
        /* wait for peer half, then immediately re-arm this stage (phase+1) */ \
        if (BUF) { MBAR_WAIT_CLUSTER(mb1, ph1); ph1 ^= 1;                      \
                   if (j == 0) MBAR_EXPECT_TX(mb1, 64 * 4); }                  \
        else     { MBAR_WAIT_CLUSTER(mb0, ph0); ph0 ^= 1;                      \
                   if (j == 0) MBAR_EXPECT_TX(mb0, 64 * 4); }                  \
        float v = __uint_as_float(((unsigned)sh_e[BUF][0]) << 16);             \
        float rho;                                                             \
        asm("rcp.approx.f32 %0, %1;" : "=f"(rho) : "f"(v));                    \
        float wr   = wexp * rho;                                               \
        float Erho = E * rho;                                                  \
        /* part B: ALL 128 peer-half states = 16 uint4, tab[64..127] */        \
        const uint4* ebB = (const uint4*)&sh_e[BUF][peer * HALF];              \
        unsigned int c2 = 0u, c3 = 0u;                                         \
        _Pragma("unroll")                                                      \
        for (int q = 0; q < 16; ++q) {                                         \
            uint4 eb = ebB[q];                                                 \
            HFMA2_BF16(c2, eb.x, tab[64 + 4 * q + 0], c2);                     \
            HFMA2_BF16(c3, eb.y, tab[64 + 4 * q + 1], c3);                     \
            HFMA2_BF16(c2, eb.z, tab[64 + 4 * q + 2], c2);                     \
            HFMA2_BF16(c3, eb.w, tab[64 + 4 * q + 3], c3);                     \
        }                                                                      \
        float accB = (__uint_as_float(c2 << 16) + __uint_as_float(c2 & 0xFFFF0000u)) \
                   + (__uint_as_float(c3 << 16) + __uint_as_float(c3 & 0xFFFF0000u)); \
        float acc = accA + accB;                                               \
        E = mv ? (acc * wr) : Erho;                                            \
        prod *= v;                                                             \
        unsigned up = __float_as_uint(prod);                                   \
        cnt += (int)(up >> 23) - 127;                                          \
        prod = __uint_as_float((up & 0x007FFFFFu) | 0x3F800000u);              \
        emit = emit_n; mv = mv_n;                                              \
    }

    // peel t = 1..3, then 127 x 4 steps
    CRF_STEP(1, 1)
    CRF_STEP(2, 0)
    CRF_STEP(3, 1)
    for (int t = 4; t < TT; t += 4) {
        CRF_STEP(t,     0)
        CRF_STEP(t + 1, 1)
        CRF_STEP(t + 2, 0)
        CRF_STEP(t + 3, 1)
    }
    #undef CRF_STEP

    // ---- per-CTA partial sum of E over my 128 columns (fixed order) ----
    float e = E;
    #pragma unroll
    for (int s = 16; s; s >>= 1) e += __shfl_xor_sync(0xFFFFFFFFu, e, s);
    if (lane == 0) sh_red[wid] = e;
    __syncthreads();
    if (j == 0) {
        float S = 0.0f;
        #pragma unroll
        for (int w = 0; w < 4; ++w) S += sh_red[w];
        g_pair[b * 2 + (int)rank] = S;
        if (rank == 0) {
            float cf = (float)cnt;
            g_nfin[b] = nbase + cf * 0.693359375f
                      + (cf * -2.1219444e-4f + __logf(prod));
            g_js[b] = js_tot;
        }
        __threadfence();
        unsigned old = atomicAdd(&g_count, 1u);
        if (old == 2u * BB - 1u) {
            g_count = 0;                  // reset for graph replays
            __threadfence();
            float ssum = 0.0f;
            #pragma unroll
            for (int x = 0; x < BB; ++x)
                ssum += g_nfin[x] + __logf(g_pair[2 * x] + g_pair[2 * x + 1]) - g_js[x];
            out[0] = ssum * (1.0f / (float)BB);
        }
    }

    // keep SMEM alive until peer consumed its final incoming writes
    asm volatile("barrier.cluster.arrive.aligned;" ::: "memory");
    asm volatile("barrier.cluster.wait.aligned;"   ::: "memory");
}

extern "C" void kernel_launch(void* const* d_in, const int* in_sizes, int n_in,
                              void* d_out, int out_size) {
    (void)in_sizes; (void)n_in; (void)out_size;
    const float* emissions = (const float*)d_in[0];
    const int*   tags      = (const int*)d_in[1];
    const int*   mask      = (const int*)d_in[2];
    const float* trans     = (const float*)d_in[3];

    crf_main<<<BB * 2, HALF>>>(emissions, tags, mask, trans, (float*)d_out);
}